// round 4
// baseline (speedup 1.0000x reference)
#include <cuda_runtime.h>

// Problem constants (fixed by the reference)
#define BB 1024
#define NN 16
#define TT 256
#define NTRI (NN * (NN + 1) / 2)   // 136
#define TPB 64                     // 64 threads = 64 (b,t) pairs, 1 thread each
#define GRID (BB * (TT / TPB))     // 4096 blocks, 4 per batch b

// Scratch for deterministic single-launch reduction (no cudaMalloc allowed)
__device__ float g_partials[GRID];
__device__ unsigned int g_count = 0;   // self-resetting arrival counter

// 16B cp.async, L1-bypass (.cg): stages global->shared without consuming
// registers or stalling the warp. This is what decouples DRAM latency from
// the register-resident factorization.
__device__ __forceinline__ void cp_async16(void* smem, const void* gmem) {
    unsigned s = (unsigned)__cvta_generic_to_shared(smem);
    asm volatile("cp.async.cg.shared.global [%0], [%1], 16;" :: "r"(s), "l"(gmem));
}
__device__ __forceinline__ void cp_async_wait_all() {
    asm volatile("cp.async.commit_group;");
    asm volatile("cp.async.wait_group 0;" ::: "memory");
}

__global__ __launch_bounds__(TPB) void gll_staged_kernel(
    const float* __restrict__ pred,
    const float* __restrict__ targ,
    const float* __restrict__ cov,
    float* __restrict__ out)
{
    // Static shared staging buffers: 136*64*4 + 2*16*64*4 = 43008 B (< 48KB)
    __shared__ __align__(16) float s_cov[NTRI][TPB];
    __shared__ __align__(16) float s_p[NN][TPB];
    __shared__ __align__(16) float s_q[NN][TPB];

    const int tid = threadIdx.x;
    const int bid = blockIdx.x;
    const int b   = bid >> 2;
    const int t0  = (bid & 3) << 6;          // this block's t range start
    const int g16 = tid >> 4;                // 16-thread group id (0..3)
    const int l16 = tid & 15;                // lane within group

    // cov plane (i,j) for this block starts at cov[((b*16+i)*16+j)*256 + t0]
    const float* covb = cov + ((size_t)b * NN * NN) * TT + t0;

    // ---- Stage cov lower triangle: plane p is 64 floats = 256B = 16 x 16B
    // chunks, handled by one 16-thread group. Fully unrolled, predicate folds.
    {
        int p = 0;
#pragma unroll
        for (int i = 0; i < NN; ++i) {
#pragma unroll
            for (int j = 0; j <= i; ++j, ++p) {
                if (g16 == (p & 3))
                    cp_async16(&s_cov[p][l16 * 4],
                               covb + (i * NN + j) * TT + l16 * 4);
            }
        }
    }
    // ---- Stage pred/targ rows for this (b, t-range)
#pragma unroll
    for (int i = 0; i < NN; ++i) {
        if (g16 == (i & 3)) {
            const size_t roff = (size_t)(b * NN + i) * TT + t0;
            cp_async16(&s_p[i][l16 * 4], pred + roff + l16 * 4);
            cp_async16(&s_q[i][l16 * 4], targ + roff + l16 * 4);
        }
    }
    cp_async_wait_all();
    __syncthreads();

    // ---- Copy my column into registers (conflict-free LDS: stride 256B rows,
    // lane l hits bank l). 64-thread blocks -> ptxas has ~180 regs/thread
    // available, so A[136]+y[16] fit with NO spills.
    float A[NTRI];
    float y[NN];
#pragma unroll
    for (int p = 0; p < NTRI; ++p) A[p] = s_cov[p][tid];
#pragma unroll
    for (int i = 0; i < NN; ++i)   y[i] = s_p[i][tid] - s_q[i][tid];

    // ---- Right-looking Cholesky, forward solve fused as augmented column.
    // Pivots >= 1 (Sigma = AA^T + I): rsqrt/log safe; pivot product stays in
    // fp32 range, so one __logf replaces 16.
    float pivprod = 1.0f;
    float quad    = 0.0f;
#pragma unroll
    for (int j = 0; j < NN; ++j) {
        const float s    = A[j * (j + 1) / 2 + j];   // pivot
        pivprod *= s;
        const float invd = rsqrtf(s);

        y[j] *= invd;
        quad = fmaf(y[j], y[j], quad);
#pragma unroll
        for (int i = j + 1; i < NN; ++i) {
            A[i * (i + 1) / 2 + j] *= invd;          // L[i][j]
        }
#pragma unroll
        for (int i = j + 1; i < NN; ++i) {
            const float lij = A[i * (i + 1) / 2 + j];
            y[i] = fmaf(-lij, y[j], y[i]);
#pragma unroll
            for (int k = j + 1; k <= i; ++k) {
                A[i * (i + 1) / 2 + k] =
                    fmaf(-lij, A[k * (k + 1) / 2 + j], A[i * (i + 1) / 2 + k]);
            }
        }
    }

    float v = quad + __logf(pivprod);

    // ---- In-block reduction: warp shuffles + 2-warp smem combine
    const int lane = tid & 31;
    const int wid  = tid >> 5;
#pragma unroll
    for (int o = 16; o > 0; o >>= 1) v += __shfl_down_sync(0xffffffffu, v, o);

    __shared__ float warpsum[TPB / 32];
    __shared__ bool  isLast;
    if (lane == 0) warpsum[wid] = v;
    __syncthreads();

    if (tid == 0) {
        float s = warpsum[0] + warpsum[1];
        g_partials[bid] = s;
        __threadfence();
        unsigned int c = atomicAdd(&g_count, 1u);
        isLast = (c == (unsigned int)(GRID - 1));
    }
    __syncthreads();

    // Last arriving block performs the deterministic final sum (fixed order).
    if (isLast) {
        float s = 0.0f;
#pragma unroll 8
        for (int i = tid; i < GRID; i += TPB) s += g_partials[i];
#pragma unroll
        for (int o = 16; o > 0; o >>= 1) s += __shfl_down_sync(0xffffffffu, s, o);
        if (lane == 0) warpsum[wid] = s;
        __syncthreads();
        if (tid == 0) {
            out[0] = (warpsum[0] + warpsum[1]) * (1.0f / (float)(BB * TT));
            g_count = 0;   // reset for the next graph replay
        }
    }
}

extern "C" void kernel_launch(void* const* d_in, const int* in_sizes, int n_in,
                              void* d_out, int out_size)
{
    const float* pred = (const float*)d_in[0];   // prediction [B,N,T]
    const float* targ = (const float*)d_in[1];   // target     [B,N,T]
    const float* cov  = (const float*)d_in[2];   // cov        [B,N,N,T]
    float* out = (float*)d_out;

    gll_staged_kernel<<<GRID, TPB>>>(pred, targ, cov, out);
}